// round 5
// baseline (speedup 1.0000x reference)
#include <cuda_runtime.h>
#include <cuda_fp16.h>
#include <cstdint>

// ---------------------------------------------------------------------------
// Shapes: x [32,256,56,56] f32, w [256,256,3,3] f32, out [32,256,56,56] f32
// ---------------------------------------------------------------------------
#define B_     32
#define CIN_   256
#define COUT_  256
#define HW_    56
#define WN_    (COUT_ * CIN_ * 9)
#define BN_EPS 1e-5f

// Scratch (allocation-free __device__ globals)
__device__ int    g_maxbits;
__device__ __half g_wqh[9 * COUT_ * CIN_];   // [tap][co][ci], s = 15*wq (odd ints, exact fp16)
__device__ float  g_scale[COUT_];            // gamma/sqrt(var+eps)/15
__device__ float  g_bias[COUT_];             // beta - mean*inv

// ---------------------------------------------------------------------------
// Prep kernels
// ---------------------------------------------------------------------------
__global__ void init_max_kernel() { g_maxbits = 0; }

__global__ void wmax_kernel(const float* __restrict__ w) {
    float m = 0.0f;
    for (int i = blockIdx.x * blockDim.x + threadIdx.x; i < WN_;
         i += gridDim.x * blockDim.x)
        m = fmaxf(m, fabsf(w[i]));
    #pragma unroll
    for (int o = 16; o > 0; o >>= 1)
        m = fmaxf(m, __shfl_xor_sync(0xFFFFFFFFu, m, o));
    if ((threadIdx.x & 31) == 0)
        atomicMax(&g_maxbits, __float_as_int(m));  // nonneg floats: int order ok
}

// s = 15*wq = 2*rint(u*15) - 15  (odd integer in [-15,15], exact in fp16)
__global__ void wquant_h_kernel(const float* __restrict__ w) {
    int i = blockIdx.x * blockDim.x + threadIdx.x;
    if (i >= WN_) return;
    float T = tanhf(__int_as_float(g_maxbits));
    float t = tanhf(w[i]);
    float u = t / (2.0f * T) + 0.5f;
    float s = 2.0f * rintf(u * 15.0f) - 15.0f;
    int tap = i % 9;
    int ci  = (i / 9) % CIN_;
    int co  = i / (9 * CIN_);
    g_wqh[(tap * COUT_ + co) * CIN_ + ci] = __float2half_rn(s);
}

__global__ void bnprep_kernel(const float* __restrict__ gamma,
                              const float* __restrict__ beta,
                              const float* __restrict__ mean,
                              const float* __restrict__ var) {
    int c = threadIdx.x;
    float inv = gamma[c] * rsqrtf(var[c] + BN_EPS);
    g_scale[c] = inv * (1.0f / 15.0f);   // conv accumulated 15x
    g_bias[c]  = beta[c] - mean[c] * inv;
}

// ---------------------------------------------------------------------------
// Warp-MMA primitives (sm_80+: legal on plain sm_103)
// ---------------------------------------------------------------------------
#define LDSM4(r, addr)                                                        \
    asm volatile("ldmatrix.sync.aligned.m8n8.x4.shared.b16 {%0,%1,%2,%3}, [%4];" \
        : "=r"((r)[0]), "=r"((r)[1]), "=r"((r)[2]), "=r"((r)[3]) : "r"(addr))

#define MMA16816(d, a, b0, b1)                                                \
    asm volatile("mma.sync.aligned.m16n8k16.row.col.f32.f16.f16.f32 "         \
        "{%0,%1,%2,%3}, {%4,%5,%6,%7}, {%8,%9}, {%0,%1,%2,%3};"               \
        : "+f"((d)[0]), "+f"((d)[1]), "+f"((d)[2]), "+f"((d)[3])              \
        : "r"((a)[0]), "r"((a)[1]), "r"((a)[2]), "r"((a)[3]), "r"(b0), "r"(b1))

static __device__ __forceinline__ void cp16(uint32_t dst, const void* src) {
    asm volatile("cp.async.cg.shared.global [%0], [%1], 16;"
                 :: "r"(dst), "l"(src));
}
#define CP_COMMIT() asm volatile("cp.async.commit_group;")
#define CP_WAIT0()  asm volatile("cp.async.wait_group 0;" ::: "memory")

// ---------------------------------------------------------------------------
// SMEM layout (bytes). X tiles: [6 rows][58 cols][40 ci-pad] fp16 (hi, lo).
// Pad 40 (80B stride) -> conflict-free ldmatrix + 16B-aligned cp.async rows.
// ---------------------------------------------------------------------------
#define RSTG   6
#define CSTG   58
#define CIPAD  40
#define XARR   (RSTG * CSTG * CIPAD * 2)    // 27840 per array
#define BOFF   (2 * XARR)                   // 55680
#define BBUF   (128 * CIPAD * 2)            // 10240 per buffer
#define BNOFF  (BOFF + 2 * BBUF)            // 76160
#define SMEM_TOT (BNOFF + 1024)             // 77184

extern __shared__ char smem[];

// ---------------------------------------------------------------------------
// Fused conv(3x3,pad1) + BN + PACT via mma.sync implicit GEMM.
// CTA: image n, 4-row band (256 px tile, 224 used), 128 c_out half.
// 8 warps = 4(M) x 2(N), warp tile 64px x 64co (128 f32 acc regs).
// K loop: 8 ci-chunks x 9 taps x 2 k16 x {hi,lo}. Taps are pure address
// offsets into the staged X tile (no A rebuild). B double-buffered cp.async.
// ---------------------------------------------------------------------------
__global__ void __launch_bounds__(256, 1)
conv_mma_kernel(const float* __restrict__ x,
                const float* __restrict__ alpha,
                float* __restrict__ out) {
    const int tid   = threadIdx.x;
    const int lane  = tid & 31;
    const int wid   = tid >> 5;
    const int warpM = wid & 3;
    const int warpN = wid >> 2;
    const int band  = blockIdx.x;        // 0..13
    const int coH   = blockIdx.y;        // 0..1
    const int n     = blockIdx.z;        // 0..31
    const int y0    = band * 4;

    const uint32_t sb = (uint32_t)__cvta_generic_to_shared(smem);
    float* sScale = (float*)(smem + BNOFF);
    float* sBias  = (float*)(smem + BNOFF + 512);
    if (tid < 128) {
        sScale[tid] = g_scale[coH * 128 + tid];
        sBias[tid]  = g_bias[coH * 128 + tid];
    }

    // per-lane ldmatrix offsets
    uint32_t aoff[4];
    #pragma unroll
    for (int mf = 0; mf < 4; ++mf) {
        int pl = warpM * 64 + mf * 16 + (lane & 15);
        if (pl > 223) pl = 223;              // clamped rows; results discarded
        int pr = pl / 56, pc = pl - pr * 56;
        aoff[mf] = (uint32_t)((pr * CSTG + pc) * (CIPAD * 2)) + ((lane >> 4) << 4);
    }
    const uint32_t boffl =
        (uint32_t)(((((lane >> 4) & 1) * 8) + (lane & 7)) * (CIPAD * 2)) +
        (((lane >> 3) & 1) << 4);

    float acc[4][8][4] = {};

    // prologue: prefetch B(tap0, chunk0) into buf0
    for (int idx = tid; idx < 512; idx += 256) {
        int co = idx >> 2, seg = idx & 3;
        cp16(sb + BOFF + co * 80 + seg * 16,
             g_wqh + ((0 * COUT_ + coH * 128 + co) * CIN_ + 0 + seg * 8));
    }
    CP_COMMIT();

    int tt = 0;
    for (int c = 0; c < 8; ++c) {
        const int ci0 = c * 32;
        __syncthreads();                       // X buffers free
        // stage X chunk: fp32 global -> fp16 hi/lo smem [r][col][ci]
        for (int i = tid; i < RSTG * CSTG * 32; i += 256) {
            int cc  = i % CSTG;
            int rst = i / CSTG;
            int r   = rst % RSTG;
            int ci  = rst / RSTG;
            int iy  = y0 - 1 + r;
            int ix  = cc - 1;
            float v = 0.0f;
            if (iy >= 0 && iy < HW_ && ix >= 0 && ix < HW_)
                v = x[((n * CIN_ + ci0 + ci) * HW_ + iy) * HW_ + ix];
            __half h = __float2half_rn(v);
            __half l = __float2half_rn(v - __half2float(h));
            int o = (r * CSTG + cc) * CIPAD + ci;
            *(unsigned short*)(smem + o * 2)        = __half_as_ushort(h);
            *(unsigned short*)(smem + XARR + o * 2) = __half_as_ushort(l);
        }
        CP_WAIT0();
        __syncthreads();

        for (int t = 0; t < 9; ++t, ++tt) {
            const int buf = tt & 1;
            // prefetch next B tile
            if (tt + 1 < 72) {
                int t2 = (tt + 1) % 9, c2 = (tt + 1) / 9;
                for (int idx = tid; idx < 512; idx += 256) {
                    int co = idx >> 2, seg = idx & 3;
                    cp16(sb + BOFF + (buf ^ 1) * BBUF + co * 80 + seg * 16,
                         g_wqh + ((t2 * COUT_ + coH * 128 + co) * CIN_ +
                                  c2 * 32 + seg * 8));
                }
            }
            CP_COMMIT();

            const int ky = t / 3, kx = t - ky * 3;
            const uint32_t dtap = (uint32_t)((ky * CSTG + kx) * (CIPAD * 2));
            const uint32_t bbase = sb + BOFF + buf * BBUF + warpN * 64 * 80 + boffl;

            #pragma unroll
            for (int ks = 0; ks < 2; ++ks) {
                uint32_t bfr[4][4];
                #pragma unroll
                for (int nf = 0; nf < 4; ++nf)
                    LDSM4(bfr[nf], bbase + nf * 16 * 80 + ks * 32);
                #pragma unroll
                for (int half = 0; half < 2; ++half) {
                    uint32_t afr[4][4];
                    const uint32_t xb = sb + half * XARR + dtap + ks * 32;
                    #pragma unroll
                    for (int mf = 0; mf < 4; ++mf)
                        LDSM4(afr[mf], xb + aoff[mf]);
                    #pragma unroll
                    for (int mf = 0; mf < 4; ++mf)
                        #pragma unroll
                        for (int nf8 = 0; nf8 < 8; ++nf8)
                            MMA16816(acc[mf][nf8], afr[mf],
                                     bfr[nf8 >> 1][(nf8 & 1) * 2],
                                     bfr[nf8 >> 1][(nf8 & 1) * 2 + 1]);
                }
            }
            CP_WAIT0();
            __syncthreads();
        }
    }

    // ---- epilogue: per-warp smem transpose + BN + PACT, coalesced stores ----
    __syncthreads();
    const float aV   = __ldg(alpha);
    const float r15a = 15.0f / aV;
    const float a15  = aV / 15.0f;
    float* sbuf = (float*)(smem + wid * 4160);   // [16 co][65 px] per warp
    const int g  = lane >> 2;
    const int tq = lane & 3;

    for (int p = 0; p < 4; ++p) {
        __syncwarp();
        #pragma unroll
        for (int j = 0; j < 2; ++j) {
            const int nf8 = p * 2 + j;
            #pragma unroll
            for (int mf = 0; mf < 4; ++mf)
                #pragma unroll
                for (int r = 0; r < 4; ++r) {
                    int pxl = mf * 16 + g + (r >> 1) * 8;
                    int col = j * 8 + tq * 2 + (r & 1);
                    sbuf[col * 65 + pxl] = acc[mf][nf8][r];
                }
        }
        __syncwarp();
        #pragma unroll
        for (int cl = 0; cl < 16; ++cl) {
            const int coc = warpN * 64 + p * 16 + cl;
            const int co  = coH * 128 + coc;
            const float sc = sScale[coc], bi = sBias[coc];
            #pragma unroll
            for (int h2 = 0; h2 < 2; ++h2) {
                int pxl = lane + h2 * 32;
                int pxg = warpM * 64 + pxl;
                if (pxg < 224) {
                    float v = sbuf[cl * 65 + pxl] * sc + bi;
                    v = fminf(fmaxf(v, 0.0f), aV);
                    v = rintf(v * r15a) * a15;
                    out[(size_t)(n * COUT_ + co) * 3136 + y0 * 56 + pxg] = v;
                }
            }
        }
    }
}

// ---------------------------------------------------------------------------
// Launch
// ---------------------------------------------------------------------------
extern "C" void kernel_launch(void* const* d_in, const int* in_sizes, int n_in,
                              void* d_out, int out_size) {
    const float* x      = (const float*)d_in[0];
    const float* weight = (const float*)d_in[1];
    const float* gamma  = (const float*)d_in[2];
    const float* beta   = (const float*)d_in[3];
    const float* rmean  = (const float*)d_in[4];
    const float* rvar   = (const float*)d_in[5];
    const float* alpha  = (const float*)d_in[6];
    float* out = (float*)d_out;

    init_max_kernel<<<1, 1>>>();
    wmax_kernel<<<576, 256>>>(weight);
    wquant_h_kernel<<<(WN_ + 255) / 256, 256>>>(weight);
    bnprep_kernel<<<1, 256>>>(gamma, beta, rmean, rvar);

    cudaFuncSetAttribute(conv_mma_kernel,
                         cudaFuncAttributeMaxDynamicSharedMemorySize, SMEM_TOT);
    dim3 grid(14, 2, B_);
    conv_mma_kernel<<<grid, 256, SMEM_TOT>>>(x, alpha, out);
}

// round 6
// speedup vs baseline: 1.8487x; 1.8487x over previous
#include <cuda_runtime.h>
#include <cstdint>

#define B_     32
#define CIN_   256
#define COUT_  256
#define HW_    56
#define WN_    (COUT_ * CIN_ * 9)
#define BN_EPS 1e-5f

typedef unsigned long long ull;

// Scratch (allocation-free __device__ globals)
__device__ int    g_maxbits;
__device__ float2 g_w2[2 * 256 * 9 * 128];  // [coHalf][ci][tap][coLocal] = (wq,wq)
__device__ float  g_scale[COUT_];
__device__ float  g_bias[COUT_];

// ---------------------------------------------------------------------------
__global__ void init_max_kernel() { g_maxbits = 0; }

__global__ void wmax_kernel(const float* __restrict__ w) {
    float m = 0.0f;
    for (int i = blockIdx.x * blockDim.x + threadIdx.x; i < WN_;
         i += gridDim.x * blockDim.x)
        m = fmaxf(m, fabsf(w[i]));
    #pragma unroll
    for (int o = 16; o > 0; o >>= 1)
        m = fmaxf(m, __shfl_xor_sync(0xFFFFFFFFu, m, o));
    if ((threadIdx.x & 31) == 0)
        atomicMax(&g_maxbits, __float_as_int(m));   // nonneg: int order ok
}

__global__ void wquant_kernel(const float* __restrict__ w) {
    int i = blockIdx.x * blockDim.x + threadIdx.x;
    if (i >= WN_) return;
    float T = tanhf(__int_as_float(g_maxbits));     // max|tanh| = tanh(max|w|)
    float t = tanhf(w[i]);
    float u = t / (2.0f * T) + 0.5f;
    float q = rintf(u * 15.0f) / 15.0f;
    float wq = 2.0f * q - 1.0f;
    int tap = i % 9;
    int ci  = (i / 9) % CIN_;
    int co  = i / (9 * CIN_);
    g_w2[(((co >> 7) * 256 + ci) * 9 + tap) * 128 + (co & 127)] =
        make_float2(wq, wq);
}

__global__ void bnprep_kernel(const float* __restrict__ gamma,
                              const float* __restrict__ beta,
                              const float* __restrict__ mean,
                              const float* __restrict__ var) {
    int c = threadIdx.x;
    float inv = gamma[c] * rsqrtf(var[c] + BN_EPS);
    g_scale[c] = inv;
    g_bias[c]  = beta[c] - mean[c] * inv;
}

// ---------------------------------------------------------------------------
#define FFMA2(d, a, b) \
    asm("fma.rn.f32x2 %0, %1, %2, %0;" : "+l"(d) : "l"(a), "l"(b))

static __device__ __forceinline__ void cp16(uint32_t dst, const void* src) {
    asm volatile("cp.async.cg.shared.global [%0], [%1], 16;"
                 :: "r"(dst), "l"(src));
}
#define CP_COMMIT() asm volatile("cp.async.commit_group;")
#define CP_WAIT0()  asm volatile("cp.async.wait_group 0;" ::: "memory")

// SMEM: W double buf [8ci][9tap][128co]f2, X double buf [8ci][5j][58s]f2,
// BN tables. coff: 40B col stride -> conflict-free lanes.
#define WD_SZ   73728
#define X2_SZ   23040
#define X2_CI   2880
#define X2_ROW  576
#define X2_OFF  (2 * WD_SZ)            // 147456
#define BN_OFF  (X2_OFF + 2 * X2_SZ)   // 193536
#define SMEM_TOT (BN_OFF + 1024)

extern __shared__ char smem[];
static __device__ __forceinline__ int coff(int s) { return (s + (s >> 2)) * 8; }

// ---------------------------------------------------------------------------
// Fused conv(3x3,pad1)+BN+PACT via packed-f32x2 FFMA2 direct conv.
// CTA: 224 thr, image n, 4-row band (2 packed row-pairs), 128-co half.
// Thread: colg=tid%14 (4 cols), cg=tid/14 (8 co) -> 64 f32x2 accumulators.
// ---------------------------------------------------------------------------
__global__ void __launch_bounds__(224)
conv_f32x2_kernel(const float* __restrict__ x,
                  const float* __restrict__ alpha,
                  float* __restrict__ out) {
    const int tid  = threadIdx.x;
    const int colg = tid % 14;
    const int cg   = tid / 14;
    const int c0   = colg * 4;
    const int co0  = cg * 8;
    const int y0   = blockIdx.x * 4;
    const int coH  = blockIdx.y;
    const int n    = blockIdx.z;

    const uint32_t sb = (uint32_t)__cvta_generic_to_shared(smem);
    float* sScale = (float*)(smem + BN_OFF);
    float* sBias  = (float*)(smem + BN_OFF + 512);
    if (tid < 128) {
        sScale[tid] = g_scale[coH * 128 + tid];
        sBias[tid]  = g_bias[coH * 128 + tid];
    }

    int xoff[6];
    #pragma unroll
    for (int m = 0; m < 6; ++m) xoff[m] = coff(c0 + m);

    ull acc[2][4][8];
    #pragma unroll
    for (int rp = 0; rp < 2; ++rp)
        #pragma unroll
        for (int cc = 0; cc < 4; ++cc)
            #pragma unroll
            for (int j8 = 0; j8 < 8; ++j8) acc[rp][cc][j8] = 0ull;

    const float2* wsrc = g_w2 + (size_t)coH * 256 * 9 * 128;
    const float*  xn   = x + (size_t)n * CIN_ * 3136;

    // ---- prologue: stage chunk 0 (X direct, W cp.async) ----
    for (int i = tid; i < 2320; i += 224) {
        int s = i % 58, j = (i / 58) % 5, ci = i / 290;
        int col = s - 1, r0 = y0 - 1 + j;
        const float* xp = xn + (size_t)ci * 3136 + col;
        bool cok = (col >= 0) & (col < HW_);
        float v0 = (cok && r0 >= 0 && r0 < HW_)     ? xp[r0 * 56]       : 0.0f;
        float v1 = (cok && r0 + 1 >= 0 && r0 + 1 < HW_) ? xp[(r0 + 1) * 56] : 0.0f;
        *(float2*)(smem + X2_OFF + ci * X2_CI + j * X2_ROW + coff(s)) =
            make_float2(v0, v1);
    }
    {
        const char* src = (const char*)wsrc;
        for (int i = tid; i < 4608; i += 224) cp16(sb + i * 16, src + i * 16);
        CP_COMMIT();
    }

    for (int ch = 0; ch < 32; ++ch) {
        const int buf = ch & 1;
        CP_WAIT0();
        __syncthreads();

        // prefetch next chunk: W async now, X LDGs into regs (STS after compute)
        float v0s[11], v1s[11];
        if (ch < 31) {
            const char* src = (const char*)(wsrc + (size_t)(ch + 1) * 8 * 9 * 128);
            uint32_t dst = sb + (buf ^ 1) * WD_SZ;
            for (int i = tid; i < 4608; i += 224) cp16(dst + i * 16, src + i * 16);
            CP_COMMIT();
            const float* xc = xn + (size_t)(ch + 1) * 8 * 3136;
            #pragma unroll
            for (int k = 0; k < 11; ++k) {
                int i = tid + k * 224;
                if (i < 2320) {
                    int s = i % 58, j = (i / 58) % 5, ci = i / 290;
                    int col = s - 1, r0 = y0 - 1 + j;
                    const float* xp = xc + (size_t)ci * 3136 + col;
                    bool cok = (col >= 0) & (col < HW_);
                    v0s[k] = (cok && r0 >= 0 && r0 < HW_)         ? xp[r0 * 56]       : 0.0f;
                    v1s[k] = (cok && r0 + 1 >= 0 && r0 + 1 < HW_) ? xp[(r0 + 1) * 56] : 0.0f;
                }
            }
        }

        // ---- compute chunk ch ----
        const char* xb = smem + X2_OFF + buf * X2_SZ;
        const char* wb = smem + buf * WD_SZ;
        for (int ci = 0; ci < 8; ++ci) {
            const char* xc = xb + ci * X2_CI;
            const char* wc = wb + ci * 9216;
            #pragma unroll
            for (int ky = 0; ky < 3; ++ky) {
                ull xa[2][6];
                #pragma unroll
                for (int r = 0; r < 2; ++r)
                    #pragma unroll
                    for (int m = 0; m < 6; ++m)
                        xa[r][m] = *(const ull*)(xc + (ky + 2 * r) * X2_ROW + xoff[m]);
                #pragma unroll
                for (int kx = 0; kx < 3; ++kx) {
                    ull wv[8];
                    const char* wt = wc + (ky * 3 + kx) * 1024 + co0 * 8;
                    #pragma unroll
                    for (int p = 0; p < 4; ++p) {
                        ulonglong2 u = *(const ulonglong2*)(wt + p * 16);
                        wv[2 * p] = u.x; wv[2 * p + 1] = u.y;
                    }
                    #pragma unroll
                    for (int rp = 0; rp < 2; ++rp)
                        #pragma unroll
                        for (int cc = 0; cc < 4; ++cc)
                            #pragma unroll
                            for (int j8 = 0; j8 < 8; ++j8)
                                FFMA2(acc[rp][cc][j8], xa[rp][cc + kx], wv[j8]);
                }
            }
        }

        // store prefetched X pairs (visible after next iteration's barrier)
        if (ch < 31) {
            char* xd = smem + X2_OFF + (buf ^ 1) * X2_SZ;
            #pragma unroll
            for (int k = 0; k < 11; ++k) {
                int i = tid + k * 224;
                if (i < 2320) {
                    int s = i % 58, j = (i / 58) % 5, ci = i / 290;
                    *(float2*)(xd + ci * X2_CI + j * X2_ROW + coff(s)) =
                        make_float2(v0s[k], v1s[k]);
                }
            }
        }
    }

    // ---- epilogue: BN + PACT, float4 stores ----
    const float aV   = __ldg(alpha);
    const float r15a = 15.0f / aV;
    const float a15  = aV / 15.0f;
    #pragma unroll
    for (int rp = 0; rp < 2; ++rp)
        #pragma unroll
        for (int j8 = 0; j8 < 8; ++j8) {
            const int co = coH * 128 + co0 + j8;
            const float sc = sScale[co0 + j8], bi = sBias[co0 + j8];
            float lo[4], hi[4];
            #pragma unroll
            for (int cc = 0; cc < 4; ++cc)
                asm("mov.b64 {%0, %1}, %2;"
                    : "=f"(lo[cc]), "=f"(hi[cc]) : "l"(acc[rp][cc][j8]));
            #pragma unroll
            for (int r = 0; r < 2; ++r) {
                float4 v4;
                float* vp = &v4.x;
                #pragma unroll
                for (int cc = 0; cc < 4; ++cc) {
                    float v = (r ? hi[cc] : lo[cc]) * sc + bi;
                    v = fminf(fmaxf(v, 0.0f), aV);
                    vp[cc] = rintf(v * r15a) * a15;
                }
                *(float4*)(out + (size_t)(n * COUT_ + co) * 3136 +
                           (y0 + 2 * rp + r) * 56 + c0) = v4;
            }
        }
}

// ---------------------------------------------------------------------------
extern "C" void kernel_launch(void* const* d_in, const int* in_sizes, int n_in,
                              void* d_out, int out_size) {
    const float* x      = (const float*)d_in[0];
    const float* weight = (const float*)d_in[1];
    const float* gamma  = (const float*)d_in[2];
    const float* beta   = (const float*)d_in[3];
    const float* rmean  = (const float*)d_in[4];
    const float* rvar   = (const float*)d_in[5];
    const float* alpha  = (const float*)d_in[6];
    float* out = (float*)d_out;

    init_max_kernel<<<1, 1>>>();
    wmax_kernel<<<576, 256>>>(weight);
    wquant_kernel<<<(WN_ + 255) / 256, 256>>>(weight);
    bnprep_kernel<<<1, 256>>>(gamma, beta, rmean, rvar);

    cudaFuncSetAttribute(conv_f32x2_kernel,
                         cudaFuncAttributeMaxDynamicSharedMemorySize, SMEM_TOT);
    dim3 grid(14, 2, B_);
    conv_f32x2_kernel<<<grid, 224, SMEM_TOT>>>(x, alpha, out);
}

// round 7
// speedup vs baseline: 2.1714x; 1.1746x over previous
#include <cuda_runtime.h>
#include <cstdint>

#define B_     32
#define CIN_   256
#define COUT_  256
#define HW_    56
#define WN_    (COUT_ * CIN_ * 9)
#define BN_EPS 1e-5f

typedef unsigned long long ull;

// Scratch (allocation-free __device__ globals)
__device__ int    g_maxbits;                // static zero-init; atomicMax idempotent
__device__ float2 g_w2[2 * 256 * 9 * 128];  // [coHalf][ci][tap][coLocal] = (wq,wq)
__device__ float  g_scale[COUT_];
__device__ float  g_bias[COUT_];

// ---------------------------------------------------------------------------
__global__ void wmax_kernel(const float* __restrict__ w) {
    float m = 0.0f;
    for (int i = blockIdx.x * blockDim.x + threadIdx.x; i < WN_;
         i += gridDim.x * blockDim.x)
        m = fmaxf(m, fabsf(w[i]));
    #pragma unroll
    for (int o = 16; o > 0; o >>= 1)
        m = fmaxf(m, __shfl_xor_sync(0xFFFFFFFFu, m, o));
    if ((threadIdx.x & 31) == 0)
        atomicMax(&g_maxbits, __float_as_int(m));   // nonneg: int order ok
}

__global__ void wquant_kernel(const float* __restrict__ w) {
    int i = blockIdx.x * blockDim.x + threadIdx.x;
    if (i >= WN_) return;
    float T = tanhf(__int_as_float(g_maxbits));     // max|tanh| = tanh(max|w|)
    float t = tanhf(w[i]);
    float u = t / (2.0f * T) + 0.5f;
    float q = rintf(u * 15.0f) / 15.0f;
    float wq = 2.0f * q - 1.0f;
    int tap = i % 9;
    int ci  = (i / 9) % CIN_;
    int co  = i / (9 * CIN_);
    g_w2[(((co >> 7) * 256 + ci) * 9 + tap) * 128 + (co & 127)] =
        make_float2(wq, wq);
}

__global__ void bnprep_kernel(const float* __restrict__ gamma,
                              const float* __restrict__ beta,
                              const float* __restrict__ mean,
                              const float* __restrict__ var) {
    int c = threadIdx.x;
    float inv = gamma[c] * rsqrtf(var[c] + BN_EPS);
    g_scale[c] = inv;
    g_bias[c]  = beta[c] - mean[c] * inv;
}

// ---------------------------------------------------------------------------
#define FFMA2(d, a, b) \
    asm("fma.rn.f32x2 %0, %1, %2, %0;" : "+l"(d) : "l"(a), "l"(b))

static __device__ __forceinline__ void cp16(uint32_t dst, const void* src) {
    asm volatile("cp.async.cg.shared.global [%0], [%1], 16;"
                 :: "r"(dst), "l"(src));
}
#define CP_COMMIT() asm volatile("cp.async.commit_group;")
#define CP_WAIT0()  asm volatile("cp.async.wait_group 0;" ::: "memory")

// SMEM: W double buf [8ci][9tap][128co]f2, X double buf [8ci][5j][58s]f2, BN.
#define WD_SZ   73728
#define X2_SZ   23040
#define X2_CI   2880
#define X2_ROW  576
#define X2_OFF  (2 * WD_SZ)            // 147456
#define BN_OFF  (X2_OFF + 2 * X2_SZ)   // 193536
#define SMEM_TOT (BN_OFF + 1024)

extern __shared__ char smem[];
static __device__ __forceinline__ int coff(int s) { return (s + (s >> 2)) * 8; }

// ---------------------------------------------------------------------------
// Fused conv(3x3,pad1)+BN+PACT, packed-f32x2 FFMA2 direct conv.
// CTA: 256 thr (8 warps, balanced), image n, 4-row band, 128-co half.
// Thread: colg=tid%8 (7 cols), cg=tid/8 (4 co), 2 row-pairs = 56 f32x2 accs.
// ---------------------------------------------------------------------------
__global__ void __launch_bounds__(256)
conv_f32x2_kernel(const float* __restrict__ x,
                  const float* __restrict__ alpha,
                  float* __restrict__ out) {
    const int tid  = threadIdx.x;
    const int colg = tid & 7;
    const int cg   = tid >> 3;           // 0..31
    const int c0   = colg * 7;
    const int co0  = cg * 4;
    const int y0   = blockIdx.x * 4;
    const int coH  = blockIdx.y;
    const int n    = blockIdx.z;

    const uint32_t sb = (uint32_t)__cvta_generic_to_shared(smem);
    float* sScale = (float*)(smem + BN_OFF);
    float* sBias  = (float*)(smem + BN_OFF + 512);
    if (tid < 128) {
        sScale[tid] = g_scale[coH * 128 + tid];
        sBias[tid]  = g_bias[coH * 128 + tid];
    }

    int xoff[9];
    #pragma unroll
    for (int m = 0; m < 9; ++m) xoff[m] = coff(c0 + m);

    ull acc[2][7][4];
    #pragma unroll
    for (int rp = 0; rp < 2; ++rp)
        #pragma unroll
        for (int cc = 0; cc < 7; ++cc)
            #pragma unroll
            for (int j8 = 0; j8 < 4; ++j8) acc[rp][cc][j8] = 0ull;

    const float2* wsrc = g_w2 + (size_t)coH * 256 * 9 * 128;
    const float*  xn   = x + (size_t)n * CIN_ * 3136;

    // ---- prologue: stage chunk 0 (X direct, W cp.async) ----
    for (int i = tid; i < 2320; i += 256) {
        int s = i % 58, j = (i / 58) % 5, ci = i / 290;
        int col = s - 1, r0 = y0 - 1 + j;
        const float* xp = xn + (size_t)ci * 3136 + col;
        bool cok = (col >= 0) & (col < HW_);
        float v0 = (cok && r0 >= 0 && r0 < HW_)         ? xp[r0 * 56]       : 0.0f;
        float v1 = (cok && r0 + 1 >= 0 && r0 + 1 < HW_) ? xp[(r0 + 1) * 56] : 0.0f;
        *(float2*)(smem + X2_OFF + ci * X2_CI + j * X2_ROW + coff(s)) =
            make_float2(v0, v1);
    }
    {
        const char* src = (const char*)wsrc;
        for (int i = tid; i < 4608; i += 256) cp16(sb + i * 16, src + i * 16);
        CP_COMMIT();
    }

    for (int ch = 0; ch < 32; ++ch) {
        const int buf = ch & 1;
        CP_WAIT0();
        __syncthreads();

        // prefetch next chunk: W async now, X LDGs into regs (STS after compute)
        float v0s[10], v1s[10];
        if (ch < 31) {
            const char* src = (const char*)(wsrc + (size_t)(ch + 1) * 8 * 9 * 128);
            uint32_t dst = sb + (buf ^ 1) * WD_SZ;
            for (int i = tid; i < 4608; i += 256) cp16(dst + i * 16, src + i * 16);
            CP_COMMIT();
            const float* xc = xn + (size_t)(ch + 1) * 8 * 3136;
            #pragma unroll
            for (int k = 0; k < 10; ++k) {
                int i = tid + k * 256;
                if (i < 2320) {
                    int s = i % 58, j = (i / 58) % 5, ci = i / 290;
                    int col = s - 1, r0 = y0 - 1 + j;
                    const float* xp = xc + (size_t)ci * 3136 + col;
                    bool cok = (col >= 0) & (col < HW_);
                    v0s[k] = (cok && r0 >= 0 && r0 < HW_)         ? xp[r0 * 56]       : 0.0f;
                    v1s[k] = (cok && r0 + 1 >= 0 && r0 + 1 < HW_) ? xp[(r0 + 1) * 56] : 0.0f;
                }
            }
        }

        // ---- compute chunk ch ----
        const char* xb = smem + X2_OFF + buf * X2_SZ;
        const char* wb = smem + buf * WD_SZ;
        for (int ci = 0; ci < 8; ++ci) {
            const char* xc = xb + ci * X2_CI;
            const char* wc = wb + ci * 9216;
            #pragma unroll
            for (int ky = 0; ky < 3; ++ky) {
                ull xa[2][9];
                #pragma unroll
                for (int r = 0; r < 2; ++r)
                    #pragma unroll
                    for (int m = 0; m < 9; ++m)
                        xa[r][m] = *(const ull*)(xc + (ky + 2 * r) * X2_ROW + xoff[m]);
                #pragma unroll
                for (int kx = 0; kx < 3; ++kx) {
                    ull wv[4];
                    const char* wt = wc + (ky * 3 + kx) * 1024 + co0 * 8;
                    {
                        ulonglong2 u0 = *(const ulonglong2*)(wt);
                        ulonglong2 u1 = *(const ulonglong2*)(wt + 16);
                        wv[0] = u0.x; wv[1] = u0.y; wv[2] = u1.x; wv[3] = u1.y;
                    }
                    #pragma unroll
                    for (int rp = 0; rp < 2; ++rp)
                        #pragma unroll
                        for (int cc = 0; cc < 7; ++cc)
                            #pragma unroll
                            for (int j8 = 0; j8 < 4; ++j8)
                                FFMA2(acc[rp][cc][j8], xa[rp][cc + kx], wv[j8]);
                }
            }
        }

        // store prefetched X pairs (visible after next iteration's barrier)
        if (ch < 31) {
            char* xd = smem + X2_OFF + (buf ^ 1) * X2_SZ;
            #pragma unroll
            for (int k = 0; k < 10; ++k) {
                int i = tid + k * 256;
                if (i < 2320) {
                    int s = i % 58, j = (i / 58) % 5, ci = i / 290;
                    *(float2*)(xd + ci * X2_CI + j * X2_ROW + coff(s)) =
                        make_float2(v0s[k], v1s[k]);
                }
            }
        }
    }

    // ---- epilogue: BN + PACT -> smem [co][228] -> coalesced float4 STG ----
    __syncthreads();                     // compute done; W/X smem reusable
    const float aV   = __ldg(alpha);
    const float r15a = 15.0f / aV;
    const float a15  = aV / 15.0f;
    float* sT = (float*)smem;            // 128 co x 228 floats = 116736 B
    #pragma unroll
    for (int j8 = 0; j8 < 4; ++j8) {
        const float sc = sScale[co0 + j8], bi = sBias[co0 + j8];
        #pragma unroll
        for (int rp = 0; rp < 2; ++rp)
            #pragma unroll
            for (int cc = 0; cc < 7; ++cc) {
                float lo, hi;
                asm("mov.b64 {%0, %1}, %2;" : "=f"(lo), "=f"(hi)
                    : "l"(acc[rp][cc][j8]));
                float v0 = fminf(fmaxf(lo * sc + bi, 0.0f), aV);
                float v1 = fminf(fmaxf(hi * sc + bi, 0.0f), aV);
                v0 = rintf(v0 * r15a) * a15;
                v1 = rintf(v1 * r15a) * a15;
                sT[(co0 + j8) * 228 + (2 * rp)     * 56 + c0 + cc] = v0;
                sT[(co0 + j8) * 228 + (2 * rp + 1) * 56 + c0 + cc] = v1;
            }
    }
    __syncthreads();
    float* ob = out + (size_t)(n * COUT_ + coH * 128) * 3136 + y0 * 56;
    #pragma unroll
    for (int k = 0; k < 28; ++k) {
        int idx = tid + k * 256;          // 0..7167
        int co = idx / 56, q = idx - co * 56;
        float4 v4 = *(float4*)(sT + co * 228 + q * 4);
        *(float4*)(ob + (size_t)co * 3136 + q * 4) = v4;
    }
}

// ---------------------------------------------------------------------------
extern "C" void kernel_launch(void* const* d_in, const int* in_sizes, int n_in,
                              void* d_out, int out_size) {
    const float* x      = (const float*)d_in[0];
    const float* weight = (const float*)d_in[1];
    const float* gamma  = (const float*)d_in[2];
    const float* beta   = (const float*)d_in[3];
    const float* rmean  = (const float*)d_in[4];
    const float* rvar   = (const float*)d_in[5];
    const float* alpha  = (const float*)d_in[6];
    float* out = (float*)d_out;

    wmax_kernel<<<576, 256>>>(weight);
    wquant_kernel<<<(WN_ + 255) / 256, 256>>>(weight);
    bnprep_kernel<<<1, 256>>>(gamma, beta, rmean, rvar);

    cudaFuncSetAttribute(conv_f32x2_kernel,
                         cudaFuncAttributeMaxDynamicSharedMemorySize, SMEM_TOT);
    dim3 grid(14, 2, B_);
    conv_f32x2_kernel<<<grid, 256, SMEM_TOT>>>(x, alpha, out);
}